// round 1
// baseline (speedup 1.0000x reference)
#include <cuda_runtime.h>
#include <mma.h>
#include <math.h>
#include <stdint.h>

using namespace nvcuda;

#define HDIM   128
#define CHUNK  32
#define AST    136      // smem row stride (floats) for 128-wide tiles
#define BMAX   16384

// ---------------- scratch (allocation-free: __device__ globals) ----------------
__device__ int   g_offs[BMAX + 1];
__device__ float g_cat [(size_t)BMAX * 256];   // [b][0:128]=v_n  [b][128:256]=s_g
__device__ float g_abuf[(size_t)BMAX * 128];   // a_b = W1 v_n + b1 + b2

__device__ __forceinline__ float sigf(float x) { return 1.0f / (1.0f + __expf(-x)); }

// ---------------- K0: prefix sum of seq_len -> g_offs ----------------
__global__ void scan_kernel(const int* __restrict__ seq, int B) {
    __shared__ int ssum[1024];
    int t = threadIdx.x;
    int C = (B + 1023) >> 10;
    int lo = t * C;
    int hi = min(lo + C, B);
    int s = 0;
    for (int i = lo; i < hi; ++i) s += seq[i];
    ssum[t] = s;
    __syncthreads();
    for (int d = 1; d < 1024; d <<= 1) {
        int v = 0;
        if (t >= d) v = ssum[t - d];
        __syncthreads();
        if (t >= d) ssum[t] += v;
        __syncthreads();
    }
    int run = (t > 0) ? ssum[t - 1] : 0;
    if (t == 0) g_offs[0] = 0;
    for (int i = lo; i < hi; ++i) { run += seq[i]; g_offs[i + 1] = run; }
}

// ---------------- K1: v_n = max(intra[last], inter[last]) into g_cat[:,0:128] ----------------
__global__ void vn_kernel(const float* __restrict__ intra, const float* __restrict__ inter, int B) {
    int b = blockIdx.x;
    if (b >= B) return;
    int j = threadIdx.x;
    int e = g_offs[b + 1];
    int last = e - 1;
    float v = 0.0f;
    if (last >= g_offs[b]) {   // len > 0
        size_t idx = (size_t)last * HDIM + j;
        v = fmaxf(intra[idx], inter[idx]);
    }
    g_cat[(size_t)b * 256 + j] = v;
}

// ---------------- generic tf32 wmma GEMM: C[M,128] = A[M,K] @ W[128,K]^T + ba (+ bb) ----------------
__global__ __launch_bounds__(256, 1)
void gemm_kernel(const float* __restrict__ A, int lda, int K,
                 const float* __restrict__ W,
                 const float* __restrict__ ba, const float* __restrict__ bb,
                 float* __restrict__ C, int M)
{
    extern __shared__ float sm[];
    const int KS = K + 8;
    float* Ws = sm;                  // [128][KS]  (tf32-converted, acts as col-major (k,n))
    float* At = Ws + 128 * KS;       // [32][KS]
    float* Zt = At + 32 * KS;        // [32][136]
    const int tid  = threadIdx.x;
    const int w    = tid >> 5;
    const int nf4  = K >> 2;

    // stage W (convert to tf32 once)
    for (int u = tid; u < 128 * nf4; u += 256) {
        int n = u / nf4, c4 = u - n * nf4;
        float4 v = *(const float4*)(W + (size_t)n * K + c4 * 4);
        float4 o;
        o.x = wmma::__float_to_tf32(v.x);
        o.y = wmma::__float_to_tf32(v.y);
        o.z = wmma::__float_to_tf32(v.z);
        o.w = wmma::__float_to_tf32(v.w);
        *(float4*)(Ws + (size_t)n * KS + c4 * 4) = o;
    }
    __syncthreads();

    const int m_t = w >> 2;
    const int n0  = (w & 3) * 2;
    const int ntiles = (M + 31) >> 5;

    for (int tile = blockIdx.x; tile < ntiles; tile += gridDim.x) {
        int row0 = tile << 5;
        int rem  = min(32, M - row0);

        for (int u = tid; u < 32 * nf4; u += 256) {
            int r = u / nf4, c4 = u - r * nf4;
            float4 o = make_float4(0.f, 0.f, 0.f, 0.f);
            if (r < rem) {
                float4 v = *(const float4*)(A + (size_t)(row0 + r) * lda + c4 * 4);
                o.x = wmma::__float_to_tf32(v.x);
                o.y = wmma::__float_to_tf32(v.y);
                o.z = wmma::__float_to_tf32(v.z);
                o.w = wmma::__float_to_tf32(v.w);
            }
            *(float4*)(At + r * KS + c4 * 4) = o;
        }
        __syncthreads();

        wmma::fragment<wmma::accumulator, 16, 16, 8, float> c0f, c1f;
        wmma::fill_fragment(c0f, 0.0f);
        wmma::fill_fragment(c1f, 0.0f);
        for (int kk = 0; kk < K; kk += 8) {
            wmma::fragment<wmma::matrix_a, 16, 16, 8, wmma::precision::tf32, wmma::row_major> af;
            wmma::load_matrix_sync(af, At + m_t * 16 * KS + kk, KS);
            wmma::fragment<wmma::matrix_b, 16, 16, 8, wmma::precision::tf32, wmma::col_major> b0f, b1f;
            wmma::load_matrix_sync(b0f, Ws + (n0 * 16) * KS + kk, KS);
            wmma::load_matrix_sync(b1f, Ws + ((n0 + 1) * 16) * KS + kk, KS);
            wmma::mma_sync(c0f, af, b0f, c0f);
            wmma::mma_sync(c1f, af, b1f, c1f);
        }
        wmma::store_matrix_sync(Zt + m_t * 16 * 136 + n0 * 16,       c0f, 136, wmma::mem_row_major);
        wmma::store_matrix_sync(Zt + m_t * 16 * 136 + (n0 + 1) * 16, c1f, 136, wmma::mem_row_major);
        __syncthreads();

        for (int u = tid; u < 32 * 128; u += 256) {
            int r = u >> 7, n = u & 127;
            if (r < rem) {
                float val = Zt[r * 136 + n] + ba[n];
                if (bb) val += bb[n];
                C[(size_t)(row0 + r) * 128 + n] = val;
            }
        }
        __syncthreads();
    }
}

// ---------------- MAIN: fused max + (hidden@W2^T) + sigmoid·q + alpha-pool ----------------
__global__ __launch_bounds__(256, 2)
void main_kernel(const float* __restrict__ intra, const float* __restrict__ inter,
                 const float* __restrict__ W2,
                 const float* __restrict__ qw, const float* __restrict__ qb, int B)
{
    extern __shared__ float sm[];
    float* W2s  = sm;                    // [128][AST] tf32 (col-major view (k,n))
    float* Asm  = W2s + 128 * AST;       // [32][AST]  fp32 hidden chunk
    float* Zsm  = Asm + 32 * AST;        // [32][AST]  mma result
    float* alph = Zsm + 32 * AST;        // [32]
    float* a_sm = alph + 32;             // [128]

    const int tid  = threadIdx.x;
    const int w    = tid >> 5;
    const int lane = tid & 31;

    // stage W2 -> tf32 smem
    for (int u = tid; u < 128 * 32; u += 256) {        // float4 units
        int n = u >> 5, c4 = u & 31;
        float4 v = *(const float4*)(W2 + (size_t)n * 128 + c4 * 4);
        float4 o;
        o.x = wmma::__float_to_tf32(v.x);
        o.y = wmma::__float_to_tf32(v.y);
        o.z = wmma::__float_to_tf32(v.z);
        o.w = wmma::__float_to_tf32(v.w);
        *(float4*)(W2s + n * AST + c4 * 4) = o;
    }
    const float q0 = qw[lane], q1 = qw[lane + 32], q2 = qw[lane + 64], q3 = qw[lane + 96];
    const float qbv = qb[0];
    __syncthreads();

    const int m_t = w >> 2;
    const int n0  = (w & 3) * 2;

    for (int b = blockIdx.x; b < B; b += gridDim.x) {
        const int start = g_offs[b];
        const int len   = g_offs[b + 1] - start;
        if (tid < 128) a_sm[tid] = g_abuf[(size_t)b * 128 + tid];
        float sg = 0.0f;
        const int nc = (len + CHUNK - 1) / CHUNK;
        __syncthreads();

        float4 pva[4], pvb[4];
        // prologue: prefetch chunk 0 (masked lanes -> 0)
        {
            const int rem0 = len;
            #pragma unroll
            for (int i = 0; i < 4; ++i) {
                int e = tid + i * 256;
                int r = e >> 5, c4 = e & 31;
                float4 za = make_float4(0.f, 0.f, 0.f, 0.f), zb = za;
                if (r < rem0) {
                    size_t off = (size_t)(start + r) * 128 + c4 * 4;
                    za = *(const float4*)(intra + off);
                    zb = *(const float4*)(inter + off);
                }
                pva[i] = za; pvb[i] = zb;
            }
        }

        for (int c = 0; c < nc; ++c) {
            // commit prefetched chunk: hidden = max, full fp32, into Asm
            #pragma unroll
            for (int i = 0; i < 4; ++i) {
                int e = tid + i * 256;
                int r = e >> 5, c4 = e & 31;
                float4 o;
                o.x = fmaxf(pva[i].x, pvb[i].x);
                o.y = fmaxf(pva[i].y, pvb[i].y);
                o.z = fmaxf(pva[i].z, pvb[i].z);
                o.w = fmaxf(pva[i].w, pvb[i].w);
                *(float4*)(Asm + r * AST + c4 * 4) = o;
            }
            __syncthreads();

            // prefetch next chunk (loads overlap the mma below; no consumer until next commit)
            if (c + 1 < nc) {
                const int base = start + (c + 1) * CHUNK;
                const int rem  = len - (c + 1) * CHUNK;
                #pragma unroll
                for (int i = 0; i < 4; ++i) {
                    int e = tid + i * 256;
                    int r = e >> 5, c4 = e & 31;
                    float4 za = make_float4(0.f, 0.f, 0.f, 0.f), zb = za;
                    if (r < rem) {
                        size_t off = (size_t)(base + r) * 128 + c4 * 4;
                        za = *(const float4*)(intra + off);
                        zb = *(const float4*)(inter + off);
                    }
                    pva[i] = za; pvb[i] = zb;
                }
            }

            // Z = hidden @ W2^T   (tf32 mma, fp32 accumulate)
            wmma::fragment<wmma::accumulator, 16, 16, 8, float> c0f, c1f;
            wmma::fill_fragment(c0f, 0.0f);
            wmma::fill_fragment(c1f, 0.0f);
            #pragma unroll
            for (int kk = 0; kk < 128; kk += 8) {
                wmma::fragment<wmma::matrix_a, 16, 16, 8, wmma::precision::tf32, wmma::row_major> af;
                wmma::load_matrix_sync(af, Asm + m_t * 16 * AST + kk, AST);
                #pragma unroll
                for (int eidx = 0; eidx < af.num_elements; ++eidx)
                    af.x[eidx] = wmma::__float_to_tf32(af.x[eidx]);
                wmma::fragment<wmma::matrix_b, 16, 16, 8, wmma::precision::tf32, wmma::col_major> b0f, b1f;
                wmma::load_matrix_sync(b0f, W2s + (n0 * 16) * AST + kk, AST);
                wmma::load_matrix_sync(b1f, W2s + ((n0 + 1) * 16) * AST + kk, AST);
                wmma::mma_sync(c0f, af, b0f, c0f);
                wmma::mma_sync(c1f, af, b1f, c1f);
            }
            wmma::store_matrix_sync(Zsm + m_t * 16 * AST + n0 * 16,       c0f, AST, wmma::mem_row_major);
            wmma::store_matrix_sync(Zsm + m_t * 16 * AST + (n0 + 1) * 16, c1f, AST, wmma::mem_row_major);
            __syncthreads();

            // alpha[t] = q · sigmoid(Z[t] + a) + qb   (warp per 4 tokens)
            #pragma unroll
            for (int tt = 0; tt < 4; ++tt) {
                int t = w * 4 + tt;
                float z0 = Zsm[t * AST + lane]      + a_sm[lane];
                float z1 = Zsm[t * AST + lane + 32] + a_sm[lane + 32];
                float z2 = Zsm[t * AST + lane + 64] + a_sm[lane + 64];
                float z3 = Zsm[t * AST + lane + 96] + a_sm[lane + 96];
                float p = sigf(z0) * q0 + sigf(z1) * q1 + sigf(z2) * q2 + sigf(z3) * q3;
                #pragma unroll
                for (int off = 16; off; off >>= 1) p += __shfl_xor_sync(0xffffffffu, p, off);
                if (lane == 0) alph[t] = p + qbv;
            }
            __syncthreads();

            // s_g += alpha[t] * hidden[t]   (fp32 hidden; padded rows are zero)
            if (tid < 128) {
                #pragma unroll 8
                for (int t = 0; t < CHUNK; ++t) sg += alph[t] * Asm[t * AST + tid];
            }
            __syncthreads();
        }
        if (tid < 128) g_cat[(size_t)b * 256 + 128 + tid] = sg;
    }
}

// ---------------- launch ----------------
#define MAIN_SMEM  ((128 * AST + 32 * AST + 32 * AST + 32 + 128) * 4)
#define GEMM_SMEM(K)  ((128 * ((K) + 8) + 32 * ((K) + 8) + 32 * 136) * 4)

extern "C" void kernel_launch(void* const* d_in, const int* in_sizes, int n_in,
                              void* d_out, int out_size)
{
    const float* intra = (const float*)d_in[0];
    const float* inter = (const float*)d_in[1];
    const float* W1    = (const float*)d_in[2];
    const float* b1    = (const float*)d_in[3];
    const float* W2    = (const float*)d_in[4];
    const float* b2    = (const float*)d_in[5];
    const float* qw    = (const float*)d_in[6];
    const float* qb    = (const float*)d_in[7];
    const float* W3    = (const float*)d_in[8];
    const float* b3    = (const float*)d_in[9];
    const int*   seq   = (const int*)d_in[10];
    const int B = in_sizes[10];

    cudaFuncSetAttribute(main_kernel, cudaFuncAttributeMaxDynamicSharedMemorySize, MAIN_SMEM);
    cudaFuncSetAttribute(gemm_kernel, cudaFuncAttributeMaxDynamicSharedMemorySize, GEMM_SMEM(256));

    float *catp = nullptr, *abufp = nullptr;
    cudaGetSymbolAddress((void**)&catp,  g_cat);
    cudaGetSymbolAddress((void**)&abufp, g_abuf);

    scan_kernel<<<1, 1024>>>(seq, B);
    vn_kernel<<<B, 128>>>(intra, inter, B);
    // a_b = v_n @ W1^T + b1 + b2
    gemm_kernel<<<148, 256, GEMM_SMEM(128)>>>(catp, 256, 128, W1, b1, b2, abufp, B);
    // fused attention pooling
    main_kernel<<<296, 256, MAIN_SMEM>>>(intra, inter, W2, qw, qb, B);
    // h_s = concat(v_n, s_g) @ W3^T + b3
    gemm_kernel<<<148, 256, GEMM_SMEM(256)>>>(catp, 256, 256, W3, b3, nullptr, (float*)d_out, B);
}

// round 2
// speedup vs baseline: 1.8534x; 1.8534x over previous
#include <cuda_runtime.h>
#include <cuda_fp16.h>
#include <mma.h>
#include <math.h>
#include <stdint.h>

using namespace nvcuda;

#define HDIM   128
#define BMAX   16384
#define TMAX   2000000

// ---------------- scratch (allocation-free: __device__ globals) ----------------
__device__ int   g_offs[BMAX + 1];
__device__ int   g_segid[TMAX];
__device__ float g_cat [(size_t)BMAX * 256];   // [b][0:128]=v_n  [b][128:256]=s_g
__device__ float g_abuf[(size_t)BMAX * 128];   // a_b = W1 v_n + b1 + b2

__device__ __forceinline__ float sigf(float x) {
    return __fdividef(1.0f, 1.0f + __expf(-x));
}

// ---------------- K0: prefix sum of seq_len -> g_offs ----------------
__global__ void scan_kernel(const int* __restrict__ seq, int B) {
    __shared__ int ssum[1024];
    int t = threadIdx.x;
    int C = (B + 1023) >> 10;
    int lo = t * C;
    int hi = min(lo + C, B);
    int s = 0;
    for (int i = lo; i < hi; ++i) s += seq[i];
    ssum[t] = s;
    __syncthreads();
    for (int d = 1; d < 1024; d <<= 1) {
        int v = 0;
        if (t >= d) v = ssum[t - d];
        __syncthreads();
        if (t >= d) ssum[t] += v;
        __syncthreads();
    }
    int run = (t > 0) ? ssum[t - 1] : 0;
    if (t == 0) g_offs[0] = 0;
    for (int i = lo; i < hi; ++i) { run += seq[i]; g_offs[i + 1] = run; }
}

// ---------------- K0b: expand seg ids ----------------
__global__ void segid_kernel(int B) {
    int b = blockIdx.x;
    if (b >= B) return;
    int s = g_offs[b], e = g_offs[b + 1];
    for (int i = s + threadIdx.x; i < e; i += blockDim.x) g_segid[i] = b;
}

// ---------------- K1: v_n gather + zero s_g ----------------
__global__ void vn_kernel(const float* __restrict__ intra, const float* __restrict__ inter, int B) {
    int b = blockIdx.x;
    if (b >= B) return;
    int j = threadIdx.x;
    int e = g_offs[b + 1];
    int last = e - 1;
    float v = 0.0f;
    if (last >= g_offs[b]) {
        size_t idx = (size_t)last * HDIM + j;
        v = fmaxf(intra[idx], inter[idx]);
    }
    g_cat[(size_t)b * 256 + j] = v;
    g_cat[(size_t)b * 256 + 128 + j] = 0.0f;   // zero s_g (accumulated by atomics)
}

// ---------------- fp16 wmma GEMM: C[M,128] = A[M,K] @ W[128,K]^T + ba (+ bb) ----------------
__global__ __launch_bounds__(256, 1)
void gemm_kernel(const float* __restrict__ A, int lda, int K,
                 const float* __restrict__ W,
                 const float* __restrict__ ba, const float* __restrict__ bb,
                 float* __restrict__ C, int M)
{
    extern __shared__ char smraw[];
    const int KS = K + 8;
    half*  Wh = (half*)smraw;                 // [128][KS]
    half*  Ah = Wh + 128 * KS;                // [32][KS]
    float* Zt = (float*)(Ah + 32 * KS);       // [32][136]
    const int tid = threadIdx.x;
    const int w   = tid >> 5;
    const int nf4 = K >> 2;

    for (int u = tid; u < 128 * nf4; u += 256) {
        int n = u / nf4, c4 = u - n * nf4;
        float4 v = *(const float4*)(W + (size_t)n * K + c4 * 4);
        half2* dst = (half2*)(Wh + (size_t)n * KS + c4 * 4);
        dst[0] = __floats2half2_rn(v.x, v.y);
        dst[1] = __floats2half2_rn(v.z, v.w);
    }
    __syncthreads();

    const int m_t = w >> 2;
    const int n0  = (w & 3) * 2;
    const int ntiles = (M + 31) >> 5;

    for (int tile = blockIdx.x; tile < ntiles; tile += gridDim.x) {
        int row0 = tile << 5;
        int rem  = min(32, M - row0);

        for (int u = tid; u < 32 * nf4; u += 256) {
            int r = u / nf4, c4 = u - r * nf4;
            float4 v = make_float4(0.f, 0.f, 0.f, 0.f);
            if (r < rem) v = *(const float4*)(A + (size_t)(row0 + r) * lda + c4 * 4);
            half2* dst = (half2*)(Ah + (size_t)r * KS + c4 * 4);
            dst[0] = __floats2half2_rn(v.x, v.y);
            dst[1] = __floats2half2_rn(v.z, v.w);
        }
        __syncthreads();

        wmma::fragment<wmma::accumulator, 16, 16, 16, float> c0f, c1f;
        wmma::fill_fragment(c0f, 0.0f);
        wmma::fill_fragment(c1f, 0.0f);
        for (int kk = 0; kk < K; kk += 16) {
            wmma::fragment<wmma::matrix_a, 16, 16, 16, half, wmma::row_major> af;
            wmma::load_matrix_sync(af, Ah + m_t * 16 * KS + kk, KS);
            wmma::fragment<wmma::matrix_b, 16, 16, 16, half, wmma::col_major> b0f, b1f;
            wmma::load_matrix_sync(b0f, Wh + (n0 * 16) * KS + kk, KS);
            wmma::load_matrix_sync(b1f, Wh + ((n0 + 1) * 16) * KS + kk, KS);
            wmma::mma_sync(c0f, af, b0f, c0f);
            wmma::mma_sync(c1f, af, b1f, c1f);
        }
        wmma::store_matrix_sync(Zt + m_t * 16 * 136 + n0 * 16,       c0f, 136, wmma::mem_row_major);
        wmma::store_matrix_sync(Zt + m_t * 16 * 136 + (n0 + 1) * 16, c1f, 136, wmma::mem_row_major);
        __syncthreads();

        for (int u = tid; u < 32 * 128; u += 256) {
            int r = u >> 7, n = u & 127;
            if (r < rem) {
                float val = Zt[r * 136 + n] + ba[n];
                if (bb) val += bb[n];
                C[(size_t)(row0 + r) * 128 + n] = val;
            }
        }
        __syncthreads();
    }
}

// ---------------- MAIN: token-parallel fused max + GEMM + sigmoid·q + segment pool ----------------
// smem layout (bytes):
//   Af  : [128][128] float   65536
//   Zs  : [128][132] float   67584
//   alph: [128]      float     512
//   W2h : [128][136] half    34816
//   Ah  : [128][136] half    34816
//   segs: [128]      int       512
#define OFF_AF   0
#define OFF_ZS   (OFF_AF + 128*128*4)
#define OFF_AL   (OFF_ZS + 128*132*4)
#define OFF_W2H  (OFF_AL + 128*4)
#define OFF_AH   (OFF_W2H + 128*136*2)
#define OFF_SEG  (OFF_AH + 128*136*2)
#define MAIN_SMEM (OFF_SEG + 128*4)

__global__ __launch_bounds__(512, 1)
void main_kernel(const float* __restrict__ intra, const float* __restrict__ inter,
                 const float* __restrict__ W2,
                 const float* __restrict__ qw, const float* __restrict__ qb,
                 const float* __restrict__ abuf, int T, int ntiles)
{
    extern __shared__ char smraw[];
    float* Af   = (float*)(smraw + OFF_AF);
    float* Zs   = (float*)(smraw + OFF_ZS);
    float* alph = (float*)(smraw + OFF_AL);
    half*  W2h  = (half*) (smraw + OFF_W2H);
    half*  Ah   = (half*) (smraw + OFF_AH);
    int*   segs = (int*)  (smraw + OFF_SEG);

    const int tid  = threadIdx.x;
    const int w    = tid >> 5;
    const int lane = tid & 31;

    // stage W2 -> fp16 smem (once per CTA)
    for (int u = tid; u < 128 * 32; u += 512) {
        int n = u >> 5, c4 = u & 31;
        float4 v = *(const float4*)(W2 + (size_t)n * 128 + c4 * 4);
        half2* dst = (half2*)(W2h + n * 136 + c4 * 4);
        dst[0] = __floats2half2_rn(v.x, v.y);
        dst[1] = __floats2half2_rn(v.z, v.w);
    }
    const float q0 = qw[lane], q1 = qw[lane + 32], q2 = qw[lane + 64], q3 = qw[lane + 96];
    const float qbv = qb[0];
    __syncthreads();

    const int m_t = w >> 1;          // 0..7  : 16-row m-tile
    const int nh  = (w & 1) * 64;    // n half

    for (int tile = blockIdx.x; tile < ntiles; tile += gridDim.x) {
        const int row0  = tile << 7;
        const int valid = min(128, T - row0);

        // ---- load + max + commit (fp32 and fp16 copies) ----
        float4 va[8], vb[8];
        #pragma unroll
        for (int i = 0; i < 8; ++i) {
            int e = tid + i * 512;
            int r = e >> 5, c4 = e & 31;
            va[i] = make_float4(0.f, 0.f, 0.f, 0.f);
            if (r < valid) va[i] = *(const float4*)(intra + (size_t)(row0 + r) * 128 + c4 * 4);
        }
        #pragma unroll
        for (int i = 0; i < 8; ++i) {
            int e = tid + i * 512;
            int r = e >> 5, c4 = e & 31;
            vb[i] = make_float4(0.f, 0.f, 0.f, 0.f);
            if (r < valid) vb[i] = *(const float4*)(inter + (size_t)(row0 + r) * 128 + c4 * 4);
        }
        if (tid < 128) segs[tid] = (tid < valid) ? g_segid[row0 + tid] : -1;
        #pragma unroll
        for (int i = 0; i < 8; ++i) {
            int e = tid + i * 512;
            int r = e >> 5, c4 = e & 31;
            float4 o;
            o.x = fmaxf(va[i].x, vb[i].x);
            o.y = fmaxf(va[i].y, vb[i].y);
            o.z = fmaxf(va[i].z, vb[i].z);
            o.w = fmaxf(va[i].w, vb[i].w);
            *(float4*)(Af + r * 128 + c4 * 4) = o;
            half2* dh = (half2*)(Ah + r * 136 + c4 * 4);
            dh[0] = __floats2half2_rn(o.x, o.y);
            dh[1] = __floats2half2_rn(o.z, o.w);
        }
        __syncthreads();

        // ---- Z = hidden @ W2^T  (fp16 mma, fp32 accumulate) ----
        {
            wmma::fragment<wmma::accumulator, 16, 16, 16, float> acc[4];
            #pragma unroll
            for (int n = 0; n < 4; ++n) wmma::fill_fragment(acc[n], 0.0f);
            #pragma unroll
            for (int kk = 0; kk < 128; kk += 16) {
                wmma::fragment<wmma::matrix_a, 16, 16, 16, half, wmma::row_major> af;
                wmma::load_matrix_sync(af, Ah + m_t * 16 * 136 + kk, 136);
                #pragma unroll
                for (int n = 0; n < 4; ++n) {
                    wmma::fragment<wmma::matrix_b, 16, 16, 16, half, wmma::col_major> bf;
                    wmma::load_matrix_sync(bf, W2h + (nh + n * 16) * 136 + kk, 136);
                    wmma::mma_sync(acc[n], af, bf, acc[n]);
                }
            }
            #pragma unroll
            for (int n = 0; n < 4; ++n)
                wmma::store_matrix_sync(Zs + m_t * 16 * 132 + nh + n * 16, acc[n], 132, wmma::mem_row_major);
        }
        __syncthreads();

        // ---- alpha[t] = q · sigmoid(Z[t] + a_b[seg(t)]) + qb  (warp per 8 tokens) ----
        #pragma unroll
        for (int tt = 0; tt < 8; ++tt) {
            int t = w * 8 + tt;
            if (t < valid) {
                const float* ab = abuf + (size_t)segs[t] * 128;
                float z0 = Zs[t * 132 + lane]      + __ldg(ab + lane);
                float z1 = Zs[t * 132 + lane + 32] + __ldg(ab + lane + 32);
                float z2 = Zs[t * 132 + lane + 64] + __ldg(ab + lane + 64);
                float z3 = Zs[t * 132 + lane + 96] + __ldg(ab + lane + 96);
                float p = sigf(z0) * q0 + sigf(z1) * q1 + sigf(z2) * q2 + sigf(z3) * q3;
                #pragma unroll
                for (int off = 16; off; off >>= 1) p += __shfl_xor_sync(0xffffffffu, p, off);
                if (lane == 0) alph[t] = p + qbv;
            } else if (lane == 0) {
                alph[t] = 0.0f;
            }
        }
        __syncthreads();

        // ---- segment pooling: 4 threads per column, 32 rows each ----
        {
            int j  = tid & 127;
            int h  = tid >> 7;
            int t0 = h * 32;
            int t1 = min(t0 + 32, valid);
            if (t0 < t1) {
                float sg = 0.0f;
                int cur = segs[t0];
                for (int t = t0; t < t1; ++t) {
                    int s = segs[t];
                    if (s != cur) {
                        atomicAdd(&g_cat[(size_t)cur * 256 + 128 + j], sg);
                        sg = 0.0f;
                        cur = s;
                    }
                    sg += alph[t] * Af[t * 128 + j];
                }
                atomicAdd(&g_cat[(size_t)cur * 256 + 128 + j], sg);
            }
        }
        __syncthreads();
    }
}

// ---------------- launch ----------------
#define GEMM_SMEM(K)  ((160 * ((K) + 8)) * 2 + 32 * 136 * 4)

extern "C" void kernel_launch(void* const* d_in, const int* in_sizes, int n_in,
                              void* d_out, int out_size)
{
    const float* intra = (const float*)d_in[0];
    const float* inter = (const float*)d_in[1];
    const float* W1    = (const float*)d_in[2];
    const float* b1    = (const float*)d_in[3];
    const float* W2    = (const float*)d_in[4];
    const float* b2    = (const float*)d_in[5];
    const float* qw    = (const float*)d_in[6];
    const float* qb    = (const float*)d_in[7];
    const float* W3    = (const float*)d_in[8];
    const float* b3    = (const float*)d_in[9];
    const int*   seq   = (const int*)d_in[10];
    const int B = in_sizes[10];
    const int T = in_sizes[0] / HDIM;
    const int ntiles = (T + 127) >> 7;

    cudaFuncSetAttribute(main_kernel, cudaFuncAttributeMaxDynamicSharedMemorySize, MAIN_SMEM);
    cudaFuncSetAttribute(gemm_kernel, cudaFuncAttributeMaxDynamicSharedMemorySize, GEMM_SMEM(256));

    float *catp = nullptr, *abufp = nullptr;
    cudaGetSymbolAddress((void**)&catp,  g_cat);
    cudaGetSymbolAddress((void**)&abufp, g_abuf);

    scan_kernel<<<1, 1024>>>(seq, B);
    segid_kernel<<<B, 64>>>(B);
    vn_kernel<<<B, 128>>>(intra, inter, B);
    // a_b = v_n @ W1^T + b1 + b2
    gemm_kernel<<<148, 256, GEMM_SMEM(128)>>>(catp, 256, 128, W1, b1, b2, abufp, B);
    // fused token-parallel attention pooling
    main_kernel<<<148, 512, MAIN_SMEM>>>(intra, inter, W2, qw, qb, abufp, T, ntiles);
    // h_s = concat(v_n, s_g) @ W3^T + b3
    gemm_kernel<<<148, 256, GEMM_SMEM(256)>>>(catp, 256, 256, W3, b3, nullptr, (float*)d_out, B);
}

// round 4
// speedup vs baseline: 2.6137x; 1.4102x over previous
#include <cuda_runtime.h>
#include <cuda_fp16.h>
#include <math.h>
#include <stdint.h>

#define HDIM   128
#define BMAX   16384
#define TMAX   2000000
#define SEGC   32          // max distinct sessions per 128-token tile for smem path

// ---------------- scratch (allocation-free: __device__ globals) ----------------
__device__ int   g_offs[BMAX + 1];
__device__ int   g_segid[TMAX];
__device__ float g_cat [(size_t)BMAX * 256];   // [b][0:128]=v_n  [b][128:256]=s_g
__device__ float g_abuf[(size_t)BMAX * 128];   // a_b = W1 v_n + b1 + b2

// sigmoid via MUFU.TANH (1 MUFU op)
__device__ __forceinline__ float sigt(float x) {
    float t;
    asm("tanh.approx.f32 %0, %1;" : "=f"(t) : "f"(0.5f * x));
    return fmaf(0.5f, t, 0.5f);
}

__device__ __forceinline__ void ldsm4(uint32_t& r0, uint32_t& r1, uint32_t& r2, uint32_t& r3, uint32_t addr) {
    asm volatile("ldmatrix.sync.aligned.m8n8.x4.shared.b16 {%0,%1,%2,%3}, [%4];\n"
                 : "=r"(r0), "=r"(r1), "=r"(r2), "=r"(r3) : "r"(addr));
}

__device__ __forceinline__ void mma16816(float* c, uint32_t a0, uint32_t a1, uint32_t a2, uint32_t a3,
                                         uint32_t b0, uint32_t b1) {
    asm volatile("mma.sync.aligned.m16n8k16.row.col.f32.f16.f16.f32 "
                 "{%0,%1,%2,%3}, {%4,%5,%6,%7}, {%8,%9}, {%0,%1,%2,%3};\n"
                 : "+f"(c[0]), "+f"(c[1]), "+f"(c[2]), "+f"(c[3])
                 : "r"(a0), "r"(a1), "r"(a2), "r"(a3), "r"(b0), "r"(b1));
}

// ---------------- K0: prefix sum of seq_len -> g_offs ----------------
__global__ void scan_kernel(const int* __restrict__ seq, int B) {
    __shared__ int ssum[1024];
    int t = threadIdx.x;
    int C = (B + 1023) >> 10;
    int lo = t * C;
    int hi = min(lo + C, B);
    int s = 0;
    for (int i = lo; i < hi; ++i) s += seq[i];
    ssum[t] = s;
    __syncthreads();
    for (int d = 1; d < 1024; d <<= 1) {
        int v = 0;
        if (t >= d) v = ssum[t - d];
        __syncthreads();
        if (t >= d) ssum[t] += v;
        __syncthreads();
    }
    int run = (t > 0) ? ssum[t - 1] : 0;
    if (t == 0) g_offs[0] = 0;
    for (int i = lo; i < hi; ++i) { run += seq[i]; g_offs[i + 1] = run; }
}

// ---------------- K0b: expand seg ids ----------------
__global__ void segid_kernel(int B) {
    int b = blockIdx.x;
    if (b >= B) return;
    int s = g_offs[b], e = g_offs[b + 1];
    for (int i = s + threadIdx.x; i < e; i += blockDim.x) g_segid[i] = b;
}

// ---------------- K1: v_n gather + zero s_g ----------------
__global__ void vn_kernel(const float* __restrict__ intra, const float* __restrict__ inter, int B) {
    int b = blockIdx.x;
    if (b >= B) return;
    int j = threadIdx.x;
    int e = g_offs[b + 1];
    int last = e - 1;
    float v = 0.0f;
    if (last >= g_offs[b]) {
        size_t idx = (size_t)last * HDIM + j;
        v = fmaxf(intra[idx], inter[idx]);
    }
    g_cat[(size_t)b * 256 + j] = v;
    g_cat[(size_t)b * 256 + 128 + j] = 0.0f;
}

// ---------------- fp16 wmma-style GEMM (small, unchanged structure) ----------------
#include <mma.h>
using namespace nvcuda;
__global__ __launch_bounds__(256, 1)
void gemm_kernel(const float* __restrict__ A, int lda, int K,
                 const float* __restrict__ W,
                 const float* __restrict__ ba, const float* __restrict__ bb,
                 float* __restrict__ C, int M)
{
    extern __shared__ char smraw[];
    const int KS = K + 8;
    half*  Wh = (half*)smraw;
    half*  Ah = Wh + 128 * KS;
    float* Zt = (float*)(Ah + 32 * KS);
    const int tid = threadIdx.x;
    const int w   = tid >> 5;
    const int nf4 = K >> 2;

    for (int u = tid; u < 128 * nf4; u += 256) {
        int n = u / nf4, c4 = u - n * nf4;
        float4 v = *(const float4*)(W + (size_t)n * K + c4 * 4);
        half2* dst = (half2*)(Wh + (size_t)n * KS + c4 * 4);
        dst[0] = __floats2half2_rn(v.x, v.y);
        dst[1] = __floats2half2_rn(v.z, v.w);
    }
    __syncthreads();

    const int m_t = w >> 2;
    const int n0  = (w & 3) * 2;
    const int ntiles = (M + 31) >> 5;

    for (int tile = blockIdx.x; tile < ntiles; tile += gridDim.x) {
        int row0 = tile << 5;
        int rem  = min(32, M - row0);

        for (int u = tid; u < 32 * nf4; u += 256) {
            int r = u / nf4, c4 = u - r * nf4;
            float4 v = make_float4(0.f, 0.f, 0.f, 0.f);
            if (r < rem) v = *(const float4*)(A + (size_t)(row0 + r) * lda + c4 * 4);
            half2* dst = (half2*)(Ah + (size_t)r * KS + c4 * 4);
            dst[0] = __floats2half2_rn(v.x, v.y);
            dst[1] = __floats2half2_rn(v.z, v.w);
        }
        __syncthreads();

        wmma::fragment<wmma::accumulator, 16, 16, 16, float> c0f, c1f;
        wmma::fill_fragment(c0f, 0.0f);
        wmma::fill_fragment(c1f, 0.0f);
        for (int kk = 0; kk < K; kk += 16) {
            wmma::fragment<wmma::matrix_a, 16, 16, 16, half, wmma::row_major> af;
            wmma::load_matrix_sync(af, Ah + m_t * 16 * KS + kk, KS);
            wmma::fragment<wmma::matrix_b, 16, 16, 16, half, wmma::col_major> b0f, b1f;
            wmma::load_matrix_sync(b0f, Wh + (n0 * 16) * KS + kk, KS);
            wmma::load_matrix_sync(b1f, Wh + ((n0 + 1) * 16) * KS + kk, KS);
            wmma::mma_sync(c0f, af, b0f, c0f);
            wmma::mma_sync(c1f, af, b1f, c1f);
        }
        wmma::store_matrix_sync(Zt + m_t * 16 * 136 + n0 * 16,       c0f, 136, wmma::mem_row_major);
        wmma::store_matrix_sync(Zt + m_t * 16 * 136 + (n0 + 1) * 16, c1f, 136, wmma::mem_row_major);
        __syncthreads();

        for (int u = tid; u < 32 * 128; u += 256) {
            int r = u >> 7, n = u & 127;
            if (r < rem) {
                float val = Zt[r * 136 + n] + ba[n];
                if (bb) val += bb[n];
                C[(size_t)(row0 + r) * 128 + n] = val;
            }
        }
        __syncthreads();
    }
}

// ---------------- MAIN: pipelined token-parallel fused kernel ----------------
// smem layout (bytes):
#define OFF_AF   0                          // [128][128] f32 : 65536
#define OFF_AH   65536                      // [128][136] f16 : 34816
#define OFF_W2H  (65536 + 34816)            // [128][136] f16 : 34816
#define OFF_ABS  (OFF_W2H + 34816)          // [SEGC][132] f32: 16896
#define OFF_PART (OFF_ABS + SEGC*132*4)     // [2][128] f32   : 1024
#define OFF_SEGS (OFF_PART + 1024)          // [128] int      : 512
#define OFF_QSM  (OFF_SEGS + 512)           // [128] f32      : 512
#define MAIN_SMEM (OFF_QSM + 512)

__global__ __launch_bounds__(512, 1)
void main_kernel(const float* __restrict__ intra, const float* __restrict__ inter,
                 const float* __restrict__ W2,
                 const float* __restrict__ qw, const float* __restrict__ qb,
                 const float* __restrict__ abuf, int T, int ntiles)
{
    extern __shared__ char smraw[];
    float* Af   = (float*)(smraw + OFF_AF);
    half*  Ah   = (half*) (smraw + OFF_AH);
    half*  W2h  = (half*) (smraw + OFF_W2H);
    float* absm = (float*)(smraw + OFF_ABS);
    float* part = (float*)(smraw + OFF_PART);    // [2][128]
    int*   segs = (int*)  (smraw + OFF_SEGS);
    float* qsm  = (float*)(smraw + OFF_QSM);

    const int tid  = threadIdx.x;
    const int w    = tid >> 5;
    const int lane = tid & 31;

    // stage W2 -> fp16 smem + q -> smem (once)
    for (int u = tid; u < 128 * 32; u += 512) {
        int n = u >> 5, c4 = u & 31;
        float4 v = *(const float4*)(W2 + (size_t)n * 128 + c4 * 4);
        half2* dst = (half2*)(W2h + n * 136 + c4 * 4);
        dst[0] = __floats2half2_rn(v.x, v.y);
        dst[1] = __floats2half2_rn(v.z, v.w);
    }
    if (tid < 128) qsm[tid] = qw[tid];
    const float qbv = qb[0];
    __syncthreads();

    const int m_t = w >> 1;           // 0..7
    const int m0  = m_t * 16;
    const int nh  = w & 1;            // 0/1 : 64-col half

    // ldmatrix per-lane shared addresses
    uint32_t ah_s = (uint32_t)__cvta_generic_to_shared(Ah);
    uint32_t w2_s = (uint32_t)__cvta_generic_to_shared(W2h);
    const int arow = (lane & 7) + ((lane >> 3) & 1) * 8;
    const int akof = ((lane >> 4) & 1) * 8;
    const uint32_t aaddr = ah_s + (uint32_t)(((m0 + arow) * 136 + akof) * 2);
    const int bn   = (lane & 7) + ((lane >> 4) & 1) * 8;
    const int bkof = ((lane >> 3) & 1) * 8;
    uint32_t baddr[4];
    #pragma unroll
    for (int p = 0; p < 4; ++p)
        baddr[p] = w2_s + (uint32_t)(((nh * 64 + p * 16 + bn) * 136 + bkof) * 2);

    // ---- prologue: prefetch first tile ----
    float4 pa[8], pb[8];
    int    psg = 0;
    int tile = blockIdx.x;
    if (tile < ntiles) {
        int row0 = tile << 7;
        int vld  = min(128, T - row0);
        #pragma unroll
        for (int i = 0; i < 8; ++i) {
            int e = tid + i * 512;
            int r = e >> 5, c4 = e & 31;
            pa[i] = make_float4(0.f, 0.f, 0.f, 0.f);
            pb[i] = pa[i];
            if (r < vld) {
                size_t off = (size_t)(row0 + r) * 128 + c4 * 4;
                pa[i] = *(const float4*)(intra + off);
                pb[i] = *(const float4*)(inter + off);
            }
        }
        if (tid < 128) psg = g_segid[min(row0 + tid, T - 1)];
    }

    for (; tile < ntiles; tile += gridDim.x) {
        // ---- commit: hidden = max -> Af (fp32) + Ah (fp16); segs ----
        #pragma unroll
        for (int i = 0; i < 8; ++i) {
            int e = tid + i * 512;
            int r = e >> 5, c4 = e & 31;
            float4 o;
            o.x = fmaxf(pa[i].x, pb[i].x);
            o.y = fmaxf(pa[i].y, pb[i].y);
            o.z = fmaxf(pa[i].z, pb[i].z);
            o.w = fmaxf(pa[i].w, pb[i].w);
            *(float4*)(Af + r * 128 + c4 * 4) = o;
            half2* dh = (half2*)(Ah + r * 136 + c4 * 4);
            dh[0] = __floats2half2_rn(o.x, o.y);
            dh[1] = __floats2half2_rn(o.z, o.w);
        }
        if (tid < 128) segs[tid] = psg;
        __syncthreads();   // A

        // ---- prefetch next tile into registers (hidden under mma) ----
        int ntile = tile + gridDim.x;
        if (ntile < ntiles) {
            int row0n = ntile << 7;
            int vldn  = min(128, T - row0n);
            #pragma unroll
            for (int i = 0; i < 8; ++i) {
                int e = tid + i * 512;
                int r = e >> 5, c4 = e & 31;
                float4 za = make_float4(0.f, 0.f, 0.f, 0.f), zb = za;
                if (r < vldn) {
                    size_t off = (size_t)(row0n + r) * 128 + c4 * 4;
                    za = *(const float4*)(intra + off);
                    zb = *(const float4*)(inter + off);
                }
                pa[i] = za; pb[i] = zb;
            }
            if (tid < 128) psg = g_segid[min(row0n + tid, T - 1)];
        }

        // ---- stage a_b rows for sessions in this tile ----
        const int seg0 = segs[0];
        const int nseg = segs[127] - seg0 + 1;
        const bool useSm = (nseg <= SEGC);
        if (useSm) {
            for (int u = tid; u < nseg * 32; u += 512) {
                int r = u >> 5, c4 = u & 31;
                *(float4*)(absm + r * 132 + c4 * 4) =
                    *(const float4*)(abuf + (size_t)(seg0 + r) * 128 + c4 * 4);
            }
        }

        // ---- mma: Z = hidden @ W2^T (fp16, fp32 acc, in registers) ----
        float acc[8][4];
        #pragma unroll
        for (int n = 0; n < 8; ++n)
            #pragma unroll
            for (int j = 0; j < 4; ++j) acc[n][j] = 0.0f;
        #pragma unroll
        for (int kk = 0; kk < 128; kk += 16) {
            uint32_t a0, a1, a2, a3;
            ldsm4(a0, a1, a2, a3, aaddr + kk * 2);
            #pragma unroll
            for (int p = 0; p < 4; ++p) {
                uint32_t b0, b1, b2, b3;
                ldsm4(b0, b1, b2, b3, baddr[p] + kk * 2);
                mma16816(acc[2 * p],     a0, a1, a2, a3, b0, b1);
                mma16816(acc[2 * p + 1], a0, a1, a2, a3, b2, b3);
            }
        }
        __syncthreads();   // B (absm visible; part safe to overwrite)

        // ---- epilogue: alpha partials from register fragments ----
        {
            const int r0 = m0 + (lane >> 2);
            const int r1 = r0 + 8;
            float p0 = 0.0f, p1 = 0.0f;
            const float* ab0;
            const float* ab1;
            if (useSm) {
                ab0 = absm + (segs[r0] - seg0) * 132;
                ab1 = absm + (segs[r1] - seg0) * 132;
            } else {
                ab0 = abuf + (size_t)segs[r0] * 128;
                ab1 = abuf + (size_t)segs[r1] * 128;
            }
            #pragma unroll
            for (int p = 0; p < 4; ++p) {
                #pragma unroll
                for (int h = 0; h < 2; ++h) {
                    const int cb = nh * 64 + p * 16 + h * 8 + (lane & 3) * 2;
                    const float* F = acc[2 * p + h];
                    float q0 = qsm[cb], q1 = qsm[cb + 1];
                    float a0v = ab0[cb], a1v = ab0[cb + 1];
                    float c0v = ab1[cb], c1v = ab1[cb + 1];
                    p0 += q0 * sigt(F[0] + a0v) + q1 * sigt(F[1] + a1v);
                    p1 += q0 * sigt(F[2] + c0v) + q1 * sigt(F[3] + c1v);
                }
            }
            p0 += __shfl_xor_sync(0xffffffffu, p0, 1);
            p0 += __shfl_xor_sync(0xffffffffu, p0, 2);
            p1 += __shfl_xor_sync(0xffffffffu, p1, 1);
            p1 += __shfl_xor_sync(0xffffffffu, p1, 2);
            if ((lane & 3) == 0) {
                part[nh * 128 + r0] = p0;
                part[nh * 128 + r1] = p1;
            }
        }
        __syncthreads();   // C

        // ---- segment pooling (4 threads per column, 32 rows each) ----
        {
            const int j  = tid & 127;
            const int h  = tid >> 7;
            const int t0 = h * 32;
            float sg = 0.0f;
            int cur = segs[t0];
            #pragma unroll 4
            for (int t = t0; t < t0 + 32; ++t) {
                int s = segs[t];
                if (s != cur) {
                    atomicAdd(&g_cat[(size_t)cur * 256 + 128 + j], sg);
                    sg = 0.0f;
                    cur = s;
                }
                float al = qbv + part[t] + part[128 + t];
                sg += al * Af[t * 128 + j];
            }
            atomicAdd(&g_cat[(size_t)cur * 256 + 128 + j], sg);
        }
        __syncthreads();   // E (protect Af/Ah/segs/absm before next commit)
    }
}

// ---------------- launch ----------------
#define GEMM_SMEM(K)  ((160 * ((K) + 8)) * 2 + 32 * 136 * 4)

extern "C" void kernel_launch(void* const* d_in, const int* in_sizes, int n_in,
                              void* d_out, int out_size)
{
    const float* intra = (const float*)d_in[0];
    const float* inter = (const float*)d_in[1];
    const float* W1    = (const float*)d_in[2];
    const float* b1    = (const float*)d_in[3];
    const float* W2    = (const float*)d_in[4];
    const float* b2    = (const float*)d_in[5];
    const float* qw    = (const float*)d_in[6];
    const float* qb    = (const float*)d_in[7];
    const float* W3    = (const float*)d_in[8];
    const float* b3    = (const float*)d_in[9];
    const int*   seq   = (const int*)d_in[10];
    const int B = in_sizes[10];
    const int T = in_sizes[0] / HDIM;
    const int ntiles = (T + 127) >> 7;

    cudaFuncSetAttribute(main_kernel, cudaFuncAttributeMaxDynamicSharedMemorySize, MAIN_SMEM);
    cudaFuncSetAttribute(gemm_kernel, cudaFuncAttributeMaxDynamicSharedMemorySize, GEMM_SMEM(256));

    float *catp = nullptr, *abufp = nullptr;
    cudaGetSymbolAddress((void**)&catp,  g_cat);
    cudaGetSymbolAddress((void**)&abufp, g_abuf);

    scan_kernel<<<1, 1024>>>(seq, B);
    segid_kernel<<<B, 64>>>(B);
    vn_kernel<<<B, 128>>>(intra, inter, B);
    gemm_kernel<<<148, 256, GEMM_SMEM(128)>>>(catp, 256, 128, W1, b1, b2, abufp, B);
    main_kernel<<<148, 512, MAIN_SMEM>>>(intra, inter, W2, qw, qb, abufp, T, ntiles);
    gemm_kernel<<<148, 256, GEMM_SMEM(256)>>>(catp, 256, 256, W3, b3, nullptr, (float*)d_out, B);
}

// round 5
// speedup vs baseline: 2.7067x; 1.0356x over previous
#include <cuda_runtime.h>
#include <cuda_fp16.h>
#include <math.h>
#include <stdint.h>

#define HDIM   128
#define BMAX   16384
#define TMAX   2000000
#define SEGC   16          // max distinct sessions per 64-token tile for smem path

// ---------------- scratch (allocation-free: __device__ globals) ----------------
__device__ int   g_offs[BMAX + 1];
__device__ int   g_segid[TMAX];
__device__ float g_cat [(size_t)BMAX * 256];   // [b][0:128]=v_n  [b][128:256]=s_g
__device__ float g_abuf[(size_t)BMAX * 128];   // a_b = W1 v_n + b1 + b2

// sigmoid via MUFU.TANH (1 MUFU op)
__device__ __forceinline__ float sigt(float x) {
    float t;
    asm("tanh.approx.f32 %0, %1;" : "=f"(t) : "f"(0.5f * x));
    return fmaf(0.5f, t, 0.5f);
}

__device__ __forceinline__ void ldsm4(uint32_t& r0, uint32_t& r1, uint32_t& r2, uint32_t& r3, uint32_t addr) {
    asm volatile("ldmatrix.sync.aligned.m8n8.x4.shared.b16 {%0,%1,%2,%3}, [%4];\n"
                 : "=r"(r0), "=r"(r1), "=r"(r2), "=r"(r3) : "r"(addr));
}

__device__ __forceinline__ void mma16816(float* c, uint32_t a0, uint32_t a1, uint32_t a2, uint32_t a3,
                                         uint32_t b0, uint32_t b1) {
    asm volatile("mma.sync.aligned.m16n8k16.row.col.f32.f16.f16.f32 "
                 "{%0,%1,%2,%3}, {%4,%5,%6,%7}, {%8,%9}, {%0,%1,%2,%3};\n"
                 : "+f"(c[0]), "+f"(c[1]), "+f"(c[2]), "+f"(c[3])
                 : "r"(a0), "r"(a1), "r"(a2), "r"(a3), "r"(b0), "r"(b1));
}

// ---------------- K0: prefix sum of seq_len -> g_offs ----------------
__global__ void scan_kernel(const int* __restrict__ seq, int B) {
    __shared__ int ssum[1024];
    int t = threadIdx.x;
    int C = (B + 1023) >> 10;
    int lo = t * C;
    int hi = min(lo + C, B);
    int s = 0;
    for (int i = lo; i < hi; ++i) s += seq[i];
    ssum[t] = s;
    __syncthreads();
    for (int d = 1; d < 1024; d <<= 1) {
        int v = 0;
        if (t >= d) v = ssum[t - d];
        __syncthreads();
        if (t >= d) ssum[t] += v;
        __syncthreads();
    }
    int run = (t > 0) ? ssum[t - 1] : 0;
    if (t == 0) g_offs[0] = 0;
    for (int i = lo; i < hi; ++i) { run += seq[i]; g_offs[i + 1] = run; }
}

// ---------------- K0b: expand seg ids ----------------
__global__ void segid_kernel(int B) {
    int b = blockIdx.x;
    if (b >= B) return;
    int s = g_offs[b], e = g_offs[b + 1];
    for (int i = s + threadIdx.x; i < e; i += blockDim.x) g_segid[i] = b;
}

// ---------------- K1: v_n gather + zero s_g ----------------
__global__ void vn_kernel(const float* __restrict__ intra, const float* __restrict__ inter, int B) {
    int b = blockIdx.x;
    if (b >= B) return;
    int j = threadIdx.x;
    int e = g_offs[b + 1];
    int last = e - 1;
    float v = 0.0f;
    if (last >= g_offs[b]) {
        size_t idx = (size_t)last * HDIM + j;
        v = fmaxf(intra[idx], inter[idx]);
    }
    g_cat[(size_t)b * 256 + j] = v;
    g_cat[(size_t)b * 256 + 128 + j] = 0.0f;
}

// ---------------- fp16 wmma GEMM (small kernels) ----------------
#include <mma.h>
using namespace nvcuda;
__global__ __launch_bounds__(256, 1)
void gemm_kernel(const float* __restrict__ A, int lda, int K,
                 const float* __restrict__ W,
                 const float* __restrict__ ba, const float* __restrict__ bb,
                 float* __restrict__ C, int M)
{
    extern __shared__ char smraw[];
    const int KS = K + 8;
    half*  Wh = (half*)smraw;
    half*  Ah = Wh + 128 * KS;
    float* Zt = (float*)(Ah + 32 * KS);
    const int tid = threadIdx.x;
    const int w   = tid >> 5;
    const int nf4 = K >> 2;

    for (int u = tid; u < 128 * nf4; u += 256) {
        int n = u / nf4, c4 = u - n * nf4;
        float4 v = *(const float4*)(W + (size_t)n * K + c4 * 4);
        half2* dst = (half2*)(Wh + (size_t)n * KS + c4 * 4);
        dst[0] = __floats2half2_rn(v.x, v.y);
        dst[1] = __floats2half2_rn(v.z, v.w);
    }
    __syncthreads();

    const int m_t = w >> 2;
    const int n0  = (w & 3) * 2;
    const int ntiles = (M + 31) >> 5;

    for (int tile = blockIdx.x; tile < ntiles; tile += gridDim.x) {
        int row0 = tile << 5;
        int rem  = min(32, M - row0);

        for (int u = tid; u < 32 * nf4; u += 256) {
            int r = u / nf4, c4 = u - r * nf4;
            float4 v = make_float4(0.f, 0.f, 0.f, 0.f);
            if (r < rem) v = *(const float4*)(A + (size_t)(row0 + r) * lda + c4 * 4);
            half2* dst = (half2*)(Ah + (size_t)r * KS + c4 * 4);
            dst[0] = __floats2half2_rn(v.x, v.y);
            dst[1] = __floats2half2_rn(v.z, v.w);
        }
        __syncthreads();

        wmma::fragment<wmma::accumulator, 16, 16, 16, float> c0f, c1f;
        wmma::fill_fragment(c0f, 0.0f);
        wmma::fill_fragment(c1f, 0.0f);
        for (int kk = 0; kk < K; kk += 16) {
            wmma::fragment<wmma::matrix_a, 16, 16, 16, half, wmma::row_major> af;
            wmma::load_matrix_sync(af, Ah + m_t * 16 * KS + kk, KS);
            wmma::fragment<wmma::matrix_b, 16, 16, 16, half, wmma::col_major> b0f, b1f;
            wmma::load_matrix_sync(b0f, Wh + (n0 * 16) * KS + kk, KS);
            wmma::load_matrix_sync(b1f, Wh + ((n0 + 1) * 16) * KS + kk, KS);
            wmma::mma_sync(c0f, af, b0f, c0f);
            wmma::mma_sync(c1f, af, b1f, c1f);
        }
        wmma::store_matrix_sync(Zt + m_t * 16 * 136 + n0 * 16,       c0f, 136, wmma::mem_row_major);
        wmma::store_matrix_sync(Zt + m_t * 16 * 136 + (n0 + 1) * 16, c1f, 136, wmma::mem_row_major);
        __syncthreads();

        for (int u = tid; u < 32 * 128; u += 256) {
            int r = u >> 7, n = u & 127;
            if (r < rem) {
                float val = Zt[r * 136 + n] + ba[n];
                if (bb) val += bb[n];
                C[(size_t)(row0 + r) * 128 + n] = val;
            }
        }
        __syncthreads();
    }
}

// ---------------- MAIN: 64-token tiles, 256 threads, 2 CTAs/SM ----------------
// smem layout (bytes):
#define OFF_AF   0                          // [64][128] f32 : 32768
#define OFF_AH   32768                      // [64][136] f16 : 17408
#define OFF_W2H  (32768 + 17408)            // [128][136] f16: 34816
#define OFF_ABS  (OFF_W2H + 34816)          // [SEGC][132] f32: 8448
#define OFF_PART (OFF_ABS + SEGC*132*4)     // [2][64] f32   : 512
#define OFF_SEGS (OFF_PART + 512)           // [64] int      : 256
#define OFF_QSM  (OFF_SEGS + 256)           // [128] f32     : 512
#define MAIN_SMEM (OFF_QSM + 512)

__global__ __launch_bounds__(256, 2)
void main_kernel(const float* __restrict__ intra, const float* __restrict__ inter,
                 const float* __restrict__ W2,
                 const float* __restrict__ qw, const float* __restrict__ qb,
                 const float* __restrict__ abuf, int T, int ntiles)
{
    extern __shared__ char smraw[];
    float* Af   = (float*)(smraw + OFF_AF);
    half*  Ah   = (half*) (smraw + OFF_AH);
    half*  W2h  = (half*) (smraw + OFF_W2H);
    float* absm = (float*)(smraw + OFF_ABS);
    float* part = (float*)(smraw + OFF_PART);    // [2][64]
    int*   segs = (int*)  (smraw + OFF_SEGS);
    float* qsm  = (float*)(smraw + OFF_QSM);

    const int tid  = threadIdx.x;
    const int w    = tid >> 5;
    const int lane = tid & 31;

    // stage W2 -> fp16 smem + q -> smem (once per CTA)
    for (int u = tid; u < 128 * 32; u += 256) {
        int n = u >> 5, c4 = u & 31;
        float4 v = *(const float4*)(W2 + (size_t)n * 128 + c4 * 4);
        half2* dst = (half2*)(W2h + n * 136 + c4 * 4);
        dst[0] = __floats2half2_rn(v.x, v.y);
        dst[1] = __floats2half2_rn(v.z, v.w);
    }
    if (tid < 128) qsm[tid] = qw[tid];
    const float qbv = qb[0];
    __syncthreads();

    const int m_t = w >> 1;           // 0..3 : 16-row m-tile within 64
    const int m0  = m_t * 16;
    const int nh  = w & 1;            // 0/1 : 64-col half

    // ldmatrix per-lane shared addresses
    uint32_t ah_s = (uint32_t)__cvta_generic_to_shared(Ah);
    uint32_t w2_s = (uint32_t)__cvta_generic_to_shared(W2h);
    const int arow = (lane & 7) + ((lane >> 3) & 1) * 8;
    const int akof = ((lane >> 4) & 1) * 8;
    const uint32_t aaddr = ah_s + (uint32_t)(((m0 + arow) * 136 + akof) * 2);
    const int bn   = (lane & 7) + ((lane >> 4) & 1) * 8;
    const int bkof = ((lane >> 3) & 1) * 8;
    uint32_t baddr[4];
    #pragma unroll
    for (int p = 0; p < 4; ++p)
        baddr[p] = w2_s + (uint32_t)(((nh * 64 + p * 16 + bn) * 136 + bkof) * 2);

    // ---- prologue: prefetch first tile ----
    float4 pa[8], pb[8];
    int    psg = 0;
    int tile = blockIdx.x;
    if (tile < ntiles) {
        int row0 = tile << 6;
        int vld  = min(64, T - row0);
        #pragma unroll
        for (int i = 0; i < 8; ++i) {
            int e = tid + i * 256;
            int r = e >> 5, c4 = e & 31;
            pa[i] = make_float4(0.f, 0.f, 0.f, 0.f);
            pb[i] = pa[i];
            if (r < vld) {
                size_t off = (size_t)(row0 + r) * 128 + c4 * 4;
                pa[i] = *(const float4*)(intra + off);
                pb[i] = *(const float4*)(inter + off);
            }
        }
        if (tid < 64) psg = g_segid[min(row0 + tid, T - 1)];
    }

    for (; tile < ntiles; tile += gridDim.x) {
        // ---- commit: hidden = max -> Af (fp32) + Ah (fp16); segs ----
        #pragma unroll
        for (int i = 0; i < 8; ++i) {
            int e = tid + i * 256;
            int r = e >> 5, c4 = e & 31;
            float4 o;
            o.x = fmaxf(pa[i].x, pb[i].x);
            o.y = fmaxf(pa[i].y, pb[i].y);
            o.z = fmaxf(pa[i].z, pb[i].z);
            o.w = fmaxf(pa[i].w, pb[i].w);
            *(float4*)(Af + r * 128 + c4 * 4) = o;
            half2* dh = (half2*)(Ah + r * 136 + c4 * 4);
            dh[0] = __floats2half2_rn(o.x, o.y);
            dh[1] = __floats2half2_rn(o.z, o.w);
        }
        if (tid < 64) segs[tid] = psg;
        __syncthreads();   // A

        // ---- prefetch next tile into registers (hides under mma) ----
        int ntile = tile + gridDim.x;
        if (ntile < ntiles) {
            int row0n = ntile << 6;
            int vldn  = min(64, T - row0n);
            #pragma unroll
            for (int i = 0; i < 8; ++i) {
                int e = tid + i * 256;
                int r = e >> 5, c4 = e & 31;
                float4 za = make_float4(0.f, 0.f, 0.f, 0.f), zb = za;
                if (r < vldn) {
                    size_t off = (size_t)(row0n + r) * 128 + c4 * 4;
                    za = *(const float4*)(intra + off);
                    zb = *(const float4*)(inter + off);
                }
                pa[i] = za; pb[i] = zb;
            }
            if (tid < 64) psg = g_segid[min(row0n + tid, T - 1)];
        }

        // ---- stage a_b rows for sessions in this tile ----
        const int seg0 = segs[0];
        const int nseg = segs[63] - seg0 + 1;
        const bool useSm = (nseg <= SEGC);
        if (useSm) {
            for (int u = tid; u < nseg * 32; u += 256) {
                int r = u >> 5, c4 = u & 31;
                *(float4*)(absm + r * 132 + c4 * 4) =
                    *(const float4*)(abuf + (size_t)(seg0 + r) * 128 + c4 * 4);
            }
        }

        // ---- mma: Z = hidden @ W2^T (fp16, fp32 acc, in registers) ----
        float acc[8][4];
        #pragma unroll
        for (int n = 0; n < 8; ++n)
            #pragma unroll
            for (int j = 0; j < 4; ++j) acc[n][j] = 0.0f;
        #pragma unroll
        for (int kk = 0; kk < 128; kk += 16) {
            uint32_t a0, a1, a2, a3;
            ldsm4(a0, a1, a2, a3, aaddr + kk * 2);
            #pragma unroll
            for (int p = 0; p < 4; ++p) {
                uint32_t b0, b1, b2, b3;
                ldsm4(b0, b1, b2, b3, baddr[p] + kk * 2);
                mma16816(acc[2 * p],     a0, a1, a2, a3, b0, b1);
                mma16816(acc[2 * p + 1], a0, a1, a2, a3, b2, b3);
            }
        }
        __syncthreads();   // B (absm visible; part safe to overwrite)

        // ---- epilogue: alpha partials from register fragments ----
        {
            const int r0 = m0 + (lane >> 2);
            const int r1 = r0 + 8;
            float p0 = 0.0f, p1 = 0.0f;
            const float* ab0;
            const float* ab1;
            if (useSm) {
                ab0 = absm + (segs[r0] - seg0) * 132;
                ab1 = absm + (segs[r1] - seg0) * 132;
            } else {
                ab0 = abuf + (size_t)segs[r0] * 128;
                ab1 = abuf + (size_t)segs[r1] * 128;
            }
            #pragma unroll
            for (int p = 0; p < 4; ++p) {
                #pragma unroll
                for (int h = 0; h < 2; ++h) {
                    const int cb = nh * 64 + p * 16 + h * 8 + (lane & 3) * 2;
                    const float* F = acc[2 * p + h];
                    float q0 = qsm[cb], q1 = qsm[cb + 1];
                    float a0v = ab0[cb], a1v = ab0[cb + 1];
                    float c0v = ab1[cb], c1v = ab1[cb + 1];
                    p0 += q0 * sigt(F[0] + a0v) + q1 * sigt(F[1] + a1v);
                    p1 += q0 * sigt(F[2] + c0v) + q1 * sigt(F[3] + c1v);
                }
            }
            p0 += __shfl_xor_sync(0xffffffffu, p0, 1);
            p0 += __shfl_xor_sync(0xffffffffu, p0, 2);
            p1 += __shfl_xor_sync(0xffffffffu, p1, 1);
            p1 += __shfl_xor_sync(0xffffffffu, p1, 2);
            if ((lane & 3) == 0) {
                part[nh * 64 + r0] = p0;
                part[nh * 64 + r1] = p1;
            }
        }
        __syncthreads();   // C

        // ---- segment pooling (2 threads per column, 32 rows each) ----
        {
            const int j  = tid & 127;
            const int h  = tid >> 7;
            const int t0 = h * 32;
            float sg = 0.0f;
            int cur = segs[t0];
            #pragma unroll 4
            for (int t = t0; t < t0 + 32; ++t) {
                int s = segs[t];
                if (s != cur) {
                    atomicAdd(&g_cat[(size_t)cur * 256 + 128 + j], sg);
                    sg = 0.0f;
                    cur = s;
                }
                float al = qbv + part[t] + part[64 + t];
                sg += al * Af[t * 128 + j];
            }
            atomicAdd(&g_cat[(size_t)cur * 256 + 128 + j], sg);
        }
        __syncthreads();   // E (protect Af/Ah/segs/absm before next commit)
    }
}

// ---------------- launch ----------------
#define GEMM_SMEM(K)  ((160 * ((K) + 8)) * 2 + 32 * 136 * 4)

extern "C" void kernel_launch(void* const* d_in, const int* in_sizes, int n_in,
                              void* d_out, int out_size)
{
    const float* intra = (const float*)d_in[0];
    const float* inter = (const float*)d_in[1];
    const float* W1    = (const float*)d_in[2];
    const float* b1    = (const float*)d_in[3];
    const float* W2    = (const float*)d_in[4];
    const float* b2    = (const float*)d_in[5];
    const float* qw    = (const float*)d_in[6];
    const float* qb    = (const float*)d_in[7];
    const float* W3    = (const float*)d_in[8];
    const float* b3    = (const float*)d_in[9];
    const int*   seq   = (const int*)d_in[10];
    const int B = in_sizes[10];
    const int T = in_sizes[0] / HDIM;
    const int ntiles = (T + 63) >> 6;

    cudaFuncSetAttribute(main_kernel, cudaFuncAttributeMaxDynamicSharedMemorySize, MAIN_SMEM);
    cudaFuncSetAttribute(gemm_kernel, cudaFuncAttributeMaxDynamicSharedMemorySize, GEMM_SMEM(256));

    float *catp = nullptr, *abufp = nullptr;
    cudaGetSymbolAddress((void**)&catp,  g_cat);
    cudaGetSymbolAddress((void**)&abufp, g_abuf);

    scan_kernel<<<1, 1024>>>(seq, B);
    segid_kernel<<<B, 64>>>(B);
    vn_kernel<<<B, 128>>>(intra, inter, B);
    gemm_kernel<<<148, 256, GEMM_SMEM(128)>>>(catp, 256, 128, W1, b1, b2, abufp, B);
    main_kernel<<<296, 256, MAIN_SMEM>>>(intra, inter, W2, qw, qb, abufp, T, ntiles);
    gemm_kernel<<<148, 256, GEMM_SMEM(256)>>>(catp, 256, 256, W3, b3, nullptr, (float*)d_out, B);
}

// round 6
// speedup vs baseline: 3.1131x; 1.1502x over previous
#include <cuda_runtime.h>
#include <cuda_fp16.h>
#include <math.h>
#include <stdint.h>

#define HDIM   128
#define BMAX   16384
#define TMAX   2000000

// ---------------- scratch (allocation-free: __device__ globals) ----------------
__device__ int   g_offs[BMAX + 1];
__device__ int   g_segid[TMAX];
__device__ float g_cat [(size_t)BMAX * 256];   // [b][0:128]=v_n  [b][128:256]=s_g
__device__ float g_abuf[(size_t)BMAX * 128];   // a_b = W1 v_n + b1 + b2

// sigmoid via MUFU.TANH
__device__ __forceinline__ float sigt(float x) {
    float t;
    asm("tanh.approx.f32 %0, %1;" : "=f"(t) : "f"(0.5f * x));
    return fmaf(0.5f, t, 0.5f);
}

__device__ __forceinline__ void ldsm4(uint32_t& r0, uint32_t& r1, uint32_t& r2, uint32_t& r3, uint32_t addr) {
    asm volatile("ldmatrix.sync.aligned.m8n8.x4.shared.b16 {%0,%1,%2,%3}, [%4];\n"
                 : "=r"(r0), "=r"(r1), "=r"(r2), "=r"(r3) : "r"(addr));
}

__device__ __forceinline__ void mma16816(float* c, uint32_t a0, uint32_t a1, uint32_t a2, uint32_t a3,
                                         uint32_t b0, uint32_t b1) {
    asm volatile("mma.sync.aligned.m16n8k16.row.col.f32.f16.f16.f32 "
                 "{%0,%1,%2,%3}, {%4,%5,%6,%7}, {%8,%9}, {%0,%1,%2,%3};\n"
                 : "+f"(c[0]), "+f"(c[1]), "+f"(c[2]), "+f"(c[3])
                 : "r"(a0), "r"(a1), "r"(a2), "r"(a3), "r"(b0), "r"(b1));
}

// ---------------- K0: prefix sum of seq_len -> g_offs ----------------
__global__ void scan_kernel(const int* __restrict__ seq, int B) {
    __shared__ int ssum[1024];
    int t = threadIdx.x;
    int C = (B + 1023) >> 10;
    int lo = t * C;
    int hi = min(lo + C, B);
    int s = 0;
    for (int i = lo; i < hi; ++i) s += seq[i];
    ssum[t] = s;
    __syncthreads();
    for (int d = 1; d < 1024; d <<= 1) {
        int v = 0;
        if (t >= d) v = ssum[t - d];
        __syncthreads();
        if (t >= d) ssum[t] += v;
        __syncthreads();
    }
    int run = (t > 0) ? ssum[t - 1] : 0;
    if (t == 0) g_offs[0] = 0;
    for (int i = lo; i < hi; ++i) { run += seq[i]; g_offs[i + 1] = run; }
}

// ---------------- K1: seg ids + v_n gather + zero s_g (merged) ----------------
__global__ void segvn_kernel(const float* __restrict__ intra, const float* __restrict__ inter, int B) {
    int b = blockIdx.x;
    if (b >= B) return;
    int j = threadIdx.x;           // 128 threads
    int s = g_offs[b], e = g_offs[b + 1];
    int last = e - 1;
    float v = 0.0f;
    if (last >= s) {
        size_t idx = (size_t)last * HDIM + j;
        v = fmaxf(intra[idx], inter[idx]);
    }
    g_cat[(size_t)b * 256 + j] = v;
    g_cat[(size_t)b * 256 + 128 + j] = 0.0f;
    for (int i = s + j; i < e; i += 128) g_segid[i] = b;
}

// ---------------- fp16 wmma GEMM (small kernels) ----------------
#include <mma.h>
using namespace nvcuda;
__global__ __launch_bounds__(256, 1)
void gemm_kernel(const float* __restrict__ A, int lda, int K,
                 const float* __restrict__ W,
                 const float* __restrict__ ba, const float* __restrict__ bb,
                 float* __restrict__ C, int M)
{
    extern __shared__ char smraw[];
    const int KS = K + 8;
    half*  Wh = (half*)smraw;
    half*  Ah = Wh + 128 * KS;
    float* Zt = (float*)(Ah + 32 * KS);
    const int tid = threadIdx.x;
    const int w   = tid >> 5;
    const int nf4 = K >> 2;

    for (int u = tid; u < 128 * nf4; u += 256) {
        int n = u / nf4, c4 = u - n * nf4;
        float4 v = *(const float4*)(W + (size_t)n * K + c4 * 4);
        half2* dst = (half2*)(Wh + (size_t)n * KS + c4 * 4);
        dst[0] = __floats2half2_rn(v.x, v.y);
        dst[1] = __floats2half2_rn(v.z, v.w);
    }
    __syncthreads();

    const int m_t = w >> 2;
    const int n0  = (w & 3) * 2;
    const int ntiles = (M + 31) >> 5;

    for (int tile = blockIdx.x; tile < ntiles; tile += gridDim.x) {
        int row0 = tile << 5;
        int rem  = min(32, M - row0);

        for (int u = tid; u < 32 * nf4; u += 256) {
            int r = u / nf4, c4 = u - r * nf4;
            float4 v = make_float4(0.f, 0.f, 0.f, 0.f);
            if (r < rem) v = *(const float4*)(A + (size_t)(row0 + r) * lda + c4 * 4);
            half2* dst = (half2*)(Ah + (size_t)r * KS + c4 * 4);
            dst[0] = __floats2half2_rn(v.x, v.y);
            dst[1] = __floats2half2_rn(v.z, v.w);
        }
        __syncthreads();

        wmma::fragment<wmma::accumulator, 16, 16, 16, float> c0f, c1f;
        wmma::fill_fragment(c0f, 0.0f);
        wmma::fill_fragment(c1f, 0.0f);
        for (int kk = 0; kk < K; kk += 16) {
            wmma::fragment<wmma::matrix_a, 16, 16, 16, half, wmma::row_major> af;
            wmma::load_matrix_sync(af, Ah + m_t * 16 * KS + kk, KS);
            wmma::fragment<wmma::matrix_b, 16, 16, 16, half, wmma::col_major> b0f, b1f;
            wmma::load_matrix_sync(b0f, Wh + (n0 * 16) * KS + kk, KS);
            wmma::load_matrix_sync(b1f, Wh + ((n0 + 1) * 16) * KS + kk, KS);
            wmma::mma_sync(c0f, af, b0f, c0f);
            wmma::mma_sync(c1f, af, b1f, c1f);
        }
        wmma::store_matrix_sync(Zt + m_t * 16 * 136 + n0 * 16,       c0f, 136, wmma::mem_row_major);
        wmma::store_matrix_sync(Zt + m_t * 16 * 136 + (n0 + 1) * 16, c1f, 136, wmma::mem_row_major);
        __syncthreads();

        for (int u = tid; u < 32 * 128; u += 256) {
            int r = u >> 7, n = u & 127;
            if (r < rem) {
                float val = Zt[r * 136 + n] + ba[n];
                if (bb) val += bb[n];
                C[(size_t)(row0 + r) * 128 + n] = val;
            }
        }
        __syncthreads();
    }
}

// ---------------- MAIN: 64-token tiles, 256 threads, 3 CTAs/SM, fp16-compressed prefetch ----------------
// smem layout (bytes):
#define OFF_AH   0                          // [64][136] f16 : 17408
#define OFF_W2H  17408                      // [128][136] f16: 34816
#define OFF_PART (OFF_W2H + 34816)          // [2][64] f32   : 512
#define OFF_SEGS (OFF_PART + 512)           // [64] int      : 256
#define OFF_QSM  (OFF_SEGS + 256)           // [128] f32     : 512
#define MAIN_SMEM (OFF_QSM + 512)

__global__ __launch_bounds__(256, 3)
void main_kernel(const float* __restrict__ intra, const float* __restrict__ inter,
                 const float* __restrict__ W2,
                 const float* __restrict__ qw, const float* __restrict__ qb,
                 const float* __restrict__ abuf, int T, int ntiles)
{
    extern __shared__ char smraw[];
    half*  Ah   = (half*) (smraw + OFF_AH);
    half*  W2h  = (half*) (smraw + OFF_W2H);
    float* part = (float*)(smraw + OFF_PART);    // [2][64]
    int*   segs = (int*)  (smraw + OFF_SEGS);
    float* qsm  = (float*)(smraw + OFF_QSM);

    const int tid  = threadIdx.x;
    const int w    = tid >> 5;
    const int lane = tid & 31;

    // stage W2 -> fp16 smem + q -> smem (once per CTA)
    for (int u = tid; u < 128 * 32; u += 256) {
        int n = u >> 5, c4 = u & 31;
        float4 v = *(const float4*)(W2 + (size_t)n * 128 + c4 * 4);
        half2* dst = (half2*)(W2h + n * 136 + c4 * 4);
        dst[0] = __floats2half2_rn(v.x, v.y);
        dst[1] = __floats2half2_rn(v.z, v.w);
    }
    if (tid < 128) qsm[tid] = qw[tid];
    const float qbv = qb[0];
    __syncthreads();

    const int m_t = w >> 1;           // 0..3 : 16-row m-tile within 64
    const int m0  = m_t * 16;
    const int nh  = w & 1;            // 0/1 : 64-col half

    // ldmatrix per-lane shared addresses
    uint32_t ah_s = (uint32_t)__cvta_generic_to_shared(Ah);
    uint32_t w2_s = (uint32_t)__cvta_generic_to_shared(W2h);
    const int arow = (lane & 7) + ((lane >> 3) & 1) * 8;
    const int akof = ((lane >> 4) & 1) * 8;
    const uint32_t aaddr = ah_s + (uint32_t)(((m0 + arow) * 136 + akof) * 2);
    const int bn   = (lane & 7) + ((lane >> 4) & 1) * 8;
    const int bkof = ((lane >> 3) & 1) * 8;
    uint32_t baddr[4];
    #pragma unroll
    for (int p = 0; p < 4; ++p)
        baddr[p] = w2_s + (uint32_t)(((nh * 64 + p * 16 + bn) * 136 + bkof) * 2);

    // ---- prologue: prefetch + compress first tile ----
    uint2 ph[8];                 // fp16 hidden, 16 regs
    int   psg = 0;
    int tile = blockIdx.x;
    if (tile < ntiles) {
        int row0 = tile << 6;
        int vld  = min(64, T - row0);
        #pragma unroll
        for (int i = 0; i < 8; ++i) {
            int e = tid + i * 256;
            int r = e >> 5, c4 = e & 31;
            float4 za = make_float4(0.f, 0.f, 0.f, 0.f), zb = za;
            if (r < vld) {
                size_t off = (size_t)(row0 + r) * 128 + c4 * 4;
                za = *(const float4*)(intra + off);
                zb = *(const float4*)(inter + off);
            }
            half2 h0 = __floats2half2_rn(fmaxf(za.x, zb.x), fmaxf(za.y, zb.y));
            half2 h1 = __floats2half2_rn(fmaxf(za.z, zb.z), fmaxf(za.w, zb.w));
            ph[i].x = *(uint32_t*)&h0;
            ph[i].y = *(uint32_t*)&h1;
        }
        if (tid < 64) psg = g_segid[min(row0 + tid, T - 1)];
    }

    for (; tile < ntiles; tile += gridDim.x) {
        // ---- commit: fp16 hidden -> Ah; segs ----
        #pragma unroll
        for (int i = 0; i < 8; ++i) {
            int e = tid + i * 256;
            int r = e >> 5, c4 = e & 31;
            *(uint2*)(Ah + r * 136 + c4 * 4) = ph[i];
        }
        if (tid < 64) segs[tid] = psg;
        __syncthreads();   // A

        // ---- prefetch + compress next tile (hides under mma) ----
        int ntile = tile + gridDim.x;
        if (ntile < ntiles) {
            int row0n = ntile << 6;
            int vldn  = min(64, T - row0n);
            #pragma unroll
            for (int i = 0; i < 8; ++i) {
                int e = tid + i * 256;
                int r = e >> 5, c4 = e & 31;
                float4 za = make_float4(0.f, 0.f, 0.f, 0.f), zb = za;
                if (r < vldn) {
                    size_t off = (size_t)(row0n + r) * 128 + c4 * 4;
                    za = *(const float4*)(intra + off);
                    zb = *(const float4*)(inter + off);
                }
                half2 h0 = __floats2half2_rn(fmaxf(za.x, zb.x), fmaxf(za.y, zb.y));
                half2 h1 = __floats2half2_rn(fmaxf(za.z, zb.z), fmaxf(za.w, zb.w));
                ph[i].x = *(uint32_t*)&h0;
                ph[i].y = *(uint32_t*)&h1;
            }
            if (tid < 64) psg = g_segid[min(row0n + tid, T - 1)];
        }

        // ---- mma: Z = hidden @ W2^T (fp16, fp32 acc, in registers) ----
        float acc[8][4];
        #pragma unroll
        for (int n = 0; n < 8; ++n)
            #pragma unroll
            for (int j = 0; j < 4; ++j) acc[n][j] = 0.0f;
        #pragma unroll
        for (int kk = 0; kk < 128; kk += 16) {
            uint32_t a0, a1, a2, a3;
            ldsm4(a0, a1, a2, a3, aaddr + kk * 2);
            #pragma unroll
            for (int p = 0; p < 4; ++p) {
                uint32_t b0, b1, b2, b3;
                ldsm4(b0, b1, b2, b3, baddr[p] + kk * 2);
                mma16816(acc[2 * p],     a0, a1, a2, a3, b0, b1);
                mma16816(acc[2 * p + 1], a0, a1, a2, a3, b2, b3);
            }
        }

        // ---- epilogue: alpha partials from register fragments ----
        {
            const int r0 = m0 + (lane >> 2);
            const int r1 = r0 + 8;
            const float* ab0 = abuf + (size_t)segs[r0] * 128;
            const float* ab1 = abuf + (size_t)segs[r1] * 128;
            float p0 = 0.0f, p1 = 0.0f;
            #pragma unroll
            for (int p = 0; p < 4; ++p) {
                #pragma unroll
                for (int h = 0; h < 2; ++h) {
                    const int cb = nh * 64 + p * 16 + h * 8 + (lane & 3) * 2;
                    const float* F = acc[2 * p + h];
                    float  q0 = qsm[cb], q1 = qsm[cb + 1];
                    float2 av = __ldg((const float2*)(ab0 + cb));
                    float2 cv = __ldg((const float2*)(ab1 + cb));
                    p0 += q0 * sigt(F[0] + av.x) + q1 * sigt(F[1] + av.y);
                    p1 += q0 * sigt(F[2] + cv.x) + q1 * sigt(F[3] + cv.y);
                }
            }
            p0 += __shfl_xor_sync(0xffffffffu, p0, 1);
            p0 += __shfl_xor_sync(0xffffffffu, p0, 2);
            p1 += __shfl_xor_sync(0xffffffffu, p1, 1);
            p1 += __shfl_xor_sync(0xffffffffu, p1, 2);
            if ((lane & 3) == 0) {
                part[nh * 64 + r0] = p0;
                part[nh * 64 + r1] = p1;
            }
        }
        __syncthreads();   // C

        // ---- segment pooling from fp16 Ah (thread = column pair, 16 rows) ----
        {
            const int j2 = tid & 63;        // half2 column index
            const int h  = tid >> 6;        // 0..3
            const int t0 = h * 16;
            float sgx = 0.0f, sgy = 0.0f;
            int cur = segs[t0];
            #pragma unroll 4
            for (int t = t0; t < t0 + 16; ++t) {
                int s = segs[t];
                if (s != cur) {
                    atomicAdd(&g_cat[(size_t)cur * 256 + 128 + 2 * j2],     sgx);
                    atomicAdd(&g_cat[(size_t)cur * 256 + 128 + 2 * j2 + 1], sgy);
                    sgx = sgy = 0.0f;
                    cur = s;
                }
                float al = qbv + part[t] + part[64 + t];
                half2 hv = *(const half2*)(Ah + t * 136 + 2 * j2);
                float2 f = __half22float2(hv);
                sgx = fmaf(al, f.x, sgx);
                sgy = fmaf(al, f.y, sgy);
            }
            atomicAdd(&g_cat[(size_t)cur * 256 + 128 + 2 * j2],     sgx);
            atomicAdd(&g_cat[(size_t)cur * 256 + 128 + 2 * j2 + 1], sgy);
        }
        __syncthreads();   // E (protect Ah/segs/part before next commit)
    }
}

// ---------------- launch ----------------
#define GEMM_SMEM(K)  ((160 * ((K) + 8)) * 2 + 32 * 136 * 4)

extern "C" void kernel_launch(void* const* d_in, const int* in_sizes, int n_in,
                              void* d_out, int out_size)
{
    const float* intra = (const float*)d_in[0];
    const float* inter = (const float*)d_in[1];
    const float* W1    = (const float*)d_in[2];
    const float* b1    = (const float*)d_in[3];
    const float* W2    = (const float*)d_in[4];
    const float* b2    = (const float*)d_in[5];
    const float* qw    = (const float*)d_in[6];
    const float* qb    = (const float*)d_in[7];
    const float* W3    = (const float*)d_in[8];
    const float* b3    = (const float*)d_in[9];
    const int*   seq   = (const int*)d_in[10];
    const int B = in_sizes[10];
    const int T = in_sizes[0] / HDIM;
    const int ntiles = (T + 63) >> 6;

    cudaFuncSetAttribute(main_kernel, cudaFuncAttributeMaxDynamicSharedMemorySize, MAIN_SMEM);
    cudaFuncSetAttribute(gemm_kernel, cudaFuncAttributeMaxDynamicSharedMemorySize, GEMM_SMEM(256));

    float *catp = nullptr, *abufp = nullptr;
    cudaGetSymbolAddress((void**)&catp,  g_cat);
    cudaGetSymbolAddress((void**)&abufp, g_abuf);

    scan_kernel<<<1, 1024>>>(seq, B);
    segvn_kernel<<<B, 128>>>(intra, inter, B);
    gemm_kernel<<<128, 256, GEMM_SMEM(128)>>>(catp, 256, 128, W1, b1, b2, abufp, B);
    main_kernel<<<444, 256, MAIN_SMEM>>>(intra, inter, W2, qw, qb, abufp, T, ntiles);
    gemm_kernel<<<128, 256, GEMM_SMEM(256)>>>(catp, 256, 256, W3, b3, nullptr, (float*)d_out, B);
}